// round 16
// baseline (speedup 1.0000x reference)
#include <cuda_runtime.h>
#include <cuda_fp16.h>
#include <cstdint>

#define B_   32768
#define FEAT 4096
#define XLD  4097
#define HID  2048
#define PROJ 512
#define NOUT 3
#define APAD (B_ + 256)
#define TILES_M 258
#define TILES_M2 129

// ---------- device scratch ----------
__device__ int g_cnt2[2];
__device__ int g_pos2row[APAD];
__device__ float g_Z[(size_t)B_ * PROJ];
__device__ __half g_A[(size_t)APAD * FEAT];      // fp16 x features, permuted rows (pad rows stay 0)
__device__ __half g_H[(size_t)APAD * HID];       // fp16 hidden
__device__ __half g_W1[(size_t)2 * 16 * 64 * 8192];   // fp16, [N][K] tile-linear SW128 (16KB tiles)
__device__ __half g_W2[(size_t)2 * 4 * 32 * 8192];

// ---------- helpers ----------
__device__ __forceinline__ uint32_t smem_u32(const void* p) {
    uint32_t a;
    asm("{ .reg .u64 t; cvta.to.shared.u64 t, %1; cvt.u32.u64 %0, t; }" : "=r"(a) : "l"(p));
    return a;
}
__device__ __forceinline__ void cpa16(uint32_t d, const void* s) {
    asm volatile("cp.async.cg.shared.global [%0], [%1], 16;" :: "r"(d), "l"(s));
}
#define CPCOMMIT() asm volatile("cp.async.commit_group;" ::: "memory")
#define CPWAIT0()  asm volatile("cp.async.wait_group 0;" ::: "memory")
#define CPWAIT1()  asm volatile("cp.async.wait_group 1;" ::: "memory")
__device__ __forceinline__ void ldsm4(uint32_t* r, uint32_t a) {
    asm volatile("ldmatrix.sync.aligned.m8n8.x4.shared.b16 {%0,%1,%2,%3}, [%4];"
                 : "=r"(r[0]), "=r"(r[1]), "=r"(r[2]), "=r"(r[3]) : "r"(a));
}
__device__ __forceinline__ void mma_h(float* c, const uint32_t* a, const uint32_t* b) {
    asm volatile("mma.sync.aligned.m16n8k16.row.col.f32.f16.f16.f32 "
                 "{%0,%1,%2,%3}, {%4,%5,%6,%7}, {%8,%9}, {%0,%1,%2,%3};"
                 : "+f"(c[0]), "+f"(c[1]), "+f"(c[2]), "+f"(c[3])
                 : "r"(a[0]), "r"(a[1]), "r"(a[2]), "r"(a[3]), "r"(b[0]), "r"(b[1]));
}

// ---------- fused partition + A convert + W prepack (block-range dispatch) ----------
__global__ __launch_bounds__(256) void k_acw(
    const float* __restrict__ x,
    const float* __restrict__ W1n, const float* __restrict__ W1o,
    const float* __restrict__ W2n, const float* __restrict__ W2o)
{
    const int t = threadIdx.x;
    if (blockIdx.x < B_) {
        const int r = blockIdx.x;
        __shared__ int sPos;
        const int m = r & 3;
        const float* base = x + (size_t)r * XLD + t * 16 - m;
        float f[20];
        float v[16];
        if (m == 0) {
            #pragma unroll
            for (int q = 0; q < 4; q++) *(float4*)(f + 4*q) = __ldg((const float4*)(base + 4*q));
            #pragma unroll
            for (int j = 0; j < 16; j++) v[j] = f[j];
        } else {
            #pragma unroll
            for (int q = 0; q < 5; q++) *(float4*)(f + 4*q) = __ldg((const float4*)(base + 4*q));
            if (m == 1) {
                #pragma unroll
                for (int j = 0; j < 16; j++) v[j] = f[j + 1];
            } else if (m == 2) {
                #pragma unroll
                for (int j = 0; j < 16; j++) v[j] = f[j + 2];
            } else {
                #pragma unroll
                for (int j = 0; j < 16; j++) v[j] = f[j + 3];
            }
        }
        if (t == 0) {
            bool nat = x[(size_t)r * XLD + FEAT] > 0.5f;
            int idx = atomicAdd(&g_cnt2[nat ? 0 : 1], 1);
            int pos = nat ? idx : (APAD - 1 - idx);
            g_pos2row[pos] = r;
            sPos = pos;
        }
        uint4 h0, h1;
        uint32_t* p0 = (uint32_t*)&h0;
        uint32_t* p1 = (uint32_t*)&h1;
        #pragma unroll
        for (int e = 0; e < 4; e++) {
            __half2 a = __floats2half2_rn(v[2*e],   v[2*e+1]);
            __half2 b = __floats2half2_rn(v[8+2*e], v[8+2*e+1]);
            p0[e] = *reinterpret_cast<uint32_t*>(&a);
            p1[e] = *reinterpret_cast<uint32_t*>(&b);
        }
        __syncthreads();
        size_t db = ((size_t)sPos * FEAT + t * 16) * 2;
        *(uint4*)((char*)g_A + db)      = h0;
        *(uint4*)((char*)g_A + db + 16) = h1;
        return;
    }

    int b = blockIdx.x - B_;
    float rv[8][4];
    if (b < 2048) {
        int tid = b * 256 + t;
        int n = (tid & 511) * 4;
        int rest = tid >> 9;
        int ko = rest & 511, g = rest >> 9;
        const float* src = (g ? W1o : W1n) + (size_t)(ko * 8) * HID + n;
        #pragma unroll
        for (int j = 0; j < 8; j++)
            *(float4*)rv[j] = __ldg((const float4*)(src + (size_t)j * HID));
        int kt = ko >> 3, cb = ko & 7;
        int nt = n >> 7;
        size_t tb = ((size_t)(((g << 4) + nt) * 64 + kt)) << 14;
        #pragma unroll
        for (int c = 0; c < 4; c++) {
            uint4 hv;
            uint32_t* hp = (uint32_t*)&hv;
            #pragma unroll
            for (int e = 0; e < 4; e++) {
                __half2 p = __floats2half2_rn(rv[2*e][c], rv[2*e+1][c]);
                hp[e] = *reinterpret_cast<uint32_t*>(&p);
            }
            int rIn = (n + c) & 127;
            uint32_t sw = (uint32_t)(rIn * 128 + (cb << 4)) ^ ((uint32_t)(rIn & 7) << 4);
            *(uint4*)((char*)g_W1 + tb + sw) = hv;
        }
    } else {
        int tid = (b - 2048) * 256 + t;
        int n = (tid & 127) * 4;
        int rest = tid >> 7;
        int ko = rest & 255, g = rest >> 8;
        const float* src = (g ? W2o : W2n) + (size_t)(ko * 8) * PROJ + n;
        #pragma unroll
        for (int j = 0; j < 8; j++)
            *(float4*)rv[j] = __ldg((const float4*)(src + (size_t)j * PROJ));
        int kt = ko >> 3, cb = ko & 7;
        int nt = n >> 7;
        size_t tb = ((size_t)(((g << 2) + nt) * 32 + kt)) << 14;
        #pragma unroll
        for (int c = 0; c < 4; c++) {
            uint4 hv;
            uint32_t* hp = (uint32_t*)&hv;
            #pragma unroll
            for (int e = 0; e < 4; e++) {
                __half2 p = __floats2half2_rn(rv[2*e][c], rv[2*e+1][c]);
                hp[e] = *reinterpret_cast<uint32_t*>(&p);
            }
            int rIn = (n + c) & 127;
            uint32_t sw = (uint32_t)(rIn * 128 + (cb << 4)) ^ ((uint32_t)(rIn & 7) << 4);
            *(uint4*)((char*)g_W2 + tb + sw) = hv;
        }
    }
}

// ---------- GEMM1: M128 x N128 CTA, warp tile 64x32, K-step 64, 3-stage, 2 CTAs/SM ----------
__global__ __launch_bounds__(256, 2) void gemm1(
    const float* __restrict__ bn_, const float* __restrict__ bo_)
{
    extern __shared__ char smc[];
    __shared__ float biasS[128];

    constexpr int STG = 32768;
    constexpr int NIT = FEAT / 64;
    const int n_nat = g_cnt2[0], n_oth = g_cnt2[1];
    const int nat_tiles = (n_nat + 127) >> 7;
    const int oth_start = (APAD - n_oth) >> 7;
    const int bm = blockIdx.y, bnb = blockIdx.x;
    int grp;
    if (bm < nat_tiles)       grp = 0;
    else if (bm >= oth_start) grp = 1;
    else return;
    const int prow0 = bm << 7;

    const int t = threadIdx.x;
    const uint32_t sb = smem_u32(smc);

    auto issue = [&](int s, int it) {
        uint32_t base = sb + s * STG;
        #pragma unroll
        for (int i = 0; i < 4; i++) {
            int cid = i * 256 + t;
            int r = cid >> 3, c = cid & 7;
            uint32_t off = (uint32_t)((r * 128 + c * 16) ^ ((r & 7) << 4));
            size_t so = ((size_t)(prow0 + r) * FEAT + it * 64 + c * 8) * 2;
            cpa16(base + off, (const char*)g_A + so);
        }
        size_t tb0 = ((size_t)(((grp << 4) + bnb) * 64 + it)) << 14;
        #pragma unroll
        for (int i = 0; i < 4; i++) {
            int j = i * 256 + t;
            cpa16(base + 16384 + j * 16, (const char*)g_W1 + tb0 + (size_t)j * 16);
        }
    };

    issue(0, 0); CPCOMMIT();
    issue(1, 1); CPCOMMIT();

    if (t < 128) biasS[t] = (grp ? bo_ : bn_)[(bnb << 7) + t];

    const int w = t >> 5, lane = t & 31;
    const int wm = w >> 2, wn = w & 3;
    const int lr = lane & 7, gq = lane >> 3;
    int preA[4], rxA[4], preB[2], rxB[2];
    #pragma unroll
    for (int mf = 0; mf < 4; mf++) {
        int row = wm * 64 + mf * 16 + (gq & 1) * 8 + lr;
        preA[mf] = row * 128 + (gq >> 1) * 16;
        rxA[mf]  = (row & 7) << 4;
    }
    #pragma unroll
    for (int p = 0; p < 2; p++) {
        int n = wn * 32 + p * 16 + (gq >> 1) * 8 + lr;
        preB[p] = (n & 127) * 128 + (gq & 1) * 16;
        rxB[p]  = (n & 7) << 4;
    }

    float acc[4][4][4];
    #pragma unroll
    for (int i = 0; i < 4; i++)
        #pragma unroll
        for (int j = 0; j < 4; j++)
            #pragma unroll
            for (int e = 0; e < 4; e++) acc[i][j][e] = 0.f;

    int buf = 0, nbuf = 2;
    for (int it = 0; it < NIT; it++) {
        if (it + 1 < NIT) { CPWAIT1(); }
        else              { CPWAIT0(); }
        __syncthreads();
        uint32_t sA = sb + buf * STG, sW = sA + 16384;
        #pragma unroll
        for (int k16 = 0; k16 < 4; k16++) {
            int kb = k16 * 32;
            uint32_t a[4][4], bb[4][2];
            #pragma unroll
            for (int mf = 0; mf < 4; mf++) ldsm4(a[mf], sA + (uint32_t)((preA[mf] + kb) ^ rxA[mf]));
            #pragma unroll
            for (int p = 0; p < 2; p++) {
                uint32_t r[4];
                ldsm4(r, sW + (uint32_t)((preB[p] + kb) ^ rxB[p]));
                bb[2*p][0]=r[0]; bb[2*p][1]=r[1]; bb[2*p+1][0]=r[2]; bb[2*p+1][1]=r[3];
            }
            #pragma unroll
            for (int mf = 0; mf < 4; mf++)
                #pragma unroll
                for (int nf = 0; nf < 4; nf++) mma_h(acc[mf][nf], a[mf], bb[nf]);
            if (k16 == 0 && it + 2 < NIT) { issue(nbuf, it + 2); CPCOMMIT(); }
        }
        buf = (buf == 2) ? 0 : buf + 1;
        nbuf = (nbuf == 2) ? 0 : nbuf + 1;
    }

    #pragma unroll
    for (int mf = 0; mf < 4; mf++) {
        #pragma unroll
        for (int half = 0; half < 2; half++) {
            int row = wm * 64 + mf * 16 + (lane >> 2) + half * 8;
            size_t base = (size_t)(prow0 + row) * HID + (bnb << 7);
            #pragma unroll
            for (int nf = 0; nf < 4; nf++) {
                int n = wn * 32 + nf * 8 + (lane & 3) * 2;
                float v0 = fmaxf(acc[mf][nf][half*2+0] + biasS[n],     0.f);
                float v1 = fmaxf(acc[mf][nf][half*2+1] + biasS[n + 1], 0.f);
                __half2 p = __floats2half2_rn(v0, v1);
                *(uint32_t*)((char*)g_H + (base + n) * 2) = *reinterpret_cast<uint32_t*>(&p);
            }
        }
    }
}

// ---------- GEMM2: M256 x N128 CTA, 512 threads (4m x 4n warps), warp tile 64x32 ----------
__global__ __launch_bounds__(512, 1) void gemm2(
    const float* __restrict__ bn_, const float* __restrict__ bo_)
{
    extern __shared__ char smc[];
    __shared__ float biasS[128];
    __shared__ int rowS[256];

    constexpr int STG = 49152;                 // A 32K + W 16K per stage; 3 stages
    constexpr int NIT = HID / 64;
    const int n_nat = g_cnt2[0], n_oth = g_cnt2[1];
    const int nat_tiles = (n_nat + 255) >> 8;
    const int oth_start = (APAD - n_oth) >> 8;
    const int bm = blockIdx.y, bnb = blockIdx.x;
    int grp;
    if (bm < nat_tiles)       grp = 0;
    else if (bm >= oth_start) grp = 1;
    else return;
    const int prow0 = bm << 8;
    const int lo = grp ? (APAD - n_oth) : 0;
    const int hi = grp ? APAD : n_nat;

    const int t = threadIdx.x;
    const uint32_t sb = smem_u32(smc);

    auto issue = [&](int s, int it) {
        uint32_t base = sb + s * STG;
        #pragma unroll
        for (int i = 0; i < 4; i++) {
            int cid = i * 512 + t;                  // 2048 cp for A (256 rows x 64k)
            int r = cid >> 3, c = cid & 7;
            uint32_t off = (uint32_t)((r * 128 + c * 16) ^ ((r & 7) << 4));
            size_t so = ((size_t)(prow0 + r) * HID + it * 64 + c * 8) * 2;
            cpa16(base + off, (const char*)g_H + so);
        }
        size_t tb0 = ((size_t)(((grp << 2) + bnb) * 32 + it)) << 14;
        #pragma unroll
        for (int i = 0; i < 2; i++) {
            int j = i * 512 + t;                    // 1024 cp for W
            cpa16(base + 32768 + j * 16, (const char*)g_W2 + tb0 + (size_t)j * 16);
        }
    };

    issue(0, 0); CPCOMMIT();
    issue(1, 1); CPCOMMIT();

    if (t < 128) biasS[t] = (grp ? bo_ : bn_)[(bnb << 7) + t];
    if (t < 256) {
        int pos = prow0 + t;
        rowS[t] = (pos >= lo && pos < hi) ? g_pos2row[pos] : -1;
    }

    const int w = t >> 5, lane = t & 31;
    const int wm = w >> 2, wn = w & 3;            // 4m x 4n warp grid
    const int lr = lane & 7, gq = lane >> 3;
    int preA[4], rxA[4], preB[2], rxB[2];
    #pragma unroll
    for (int mf = 0; mf < 4; mf++) {
        int row = wm * 64 + mf * 16 + (gq & 1) * 8 + lr;
        preA[mf] = row * 128 + (gq >> 1) * 16;
        rxA[mf]  = (row & 7) << 4;
    }
    #pragma unroll
    for (int p = 0; p < 2; p++) {
        int n = wn * 32 + p * 16 + (gq >> 1) * 8 + lr;
        preB[p] = (n & 127) * 128 + (gq & 1) * 16;
        rxB[p]  = (n & 7) << 4;
    }

    float acc[4][4][4];
    #pragma unroll
    for (int i = 0; i < 4; i++)
        #pragma unroll
        for (int j = 0; j < 4; j++)
            #pragma unroll
            for (int e = 0; e < 4; e++) acc[i][j][e] = 0.f;

    int buf = 0, nbuf = 2;
    for (int it = 0; it < NIT; it++) {
        if (it + 1 < NIT) { CPWAIT1(); }
        else              { CPWAIT0(); }
        __syncthreads();
        uint32_t sA = sb + buf * STG, sW = sA + 32768;
        #pragma unroll
        for (int k16 = 0; k16 < 4; k16++) {
            int kb = k16 * 32;
            uint32_t a[4][4], bb[4][2];
            #pragma unroll
            for (int mf = 0; mf < 4; mf++) ldsm4(a[mf], sA + (uint32_t)((preA[mf] + kb) ^ rxA[mf]));
            #pragma unroll
            for (int p = 0; p < 2; p++) {
                uint32_t r[4];
                ldsm4(r, sW + (uint32_t)((preB[p] + kb) ^ rxB[p]));
                bb[2*p][0]=r[0]; bb[2*p][1]=r[1]; bb[2*p+1][0]=r[2]; bb[2*p+1][1]=r[3];
            }
            #pragma unroll
            for (int mf = 0; mf < 4; mf++)
                #pragma unroll
                for (int nf = 0; nf < 4; nf++) mma_h(acc[mf][nf], a[mf], bb[nf]);
            if (k16 == 0 && it + 2 < NIT) { issue(nbuf, it + 2); CPCOMMIT(); }
        }
        buf = (buf == 2) ? 0 : buf + 1;
        nbuf = (nbuf == 2) ? 0 : nbuf + 1;
    }

    #pragma unroll
    for (int mf = 0; mf < 4; mf++) {
        #pragma unroll
        for (int half = 0; half < 2; half++) {
            int row = wm * 64 + mf * 16 + (lane >> 2) + half * 8;
            int orig = rowS[row];
            if (orig >= 0) {
                float* zp = g_Z + (size_t)orig * PROJ + (bnb << 7);
                #pragma unroll
                for (int nf = 0; nf < 4; nf++) {
                    int n = wn * 32 + nf * 8 + (lane & 3) * 2;
                    float2 v;
                    v.x = acc[mf][nf][half*2+0] + biasS[n];
                    v.y = acc[mf][nf][half*2+1] + biasS[n + 1];
                    *(float2*)(zp + n) = v;
                }
            }
        }
    }
}

// ---------- finalize: warp-per-row norm + logits; resets counters for next replay ----------
__global__ __launch_bounds__(256) void k_final(
    const float* __restrict__ x,
    const float* __restrict__ Wcn, const float* __restrict__ bcn,
    const float* __restrict__ Wco, const float* __restrict__ bco,
    float* __restrict__ out)
{
    if (blockIdx.x == 0 && threadIdx.x == 0) {
        g_cnt2[0] = 0; g_cnt2[1] = 0;
    }
    const int wid = threadIdx.x >> 5, lane = threadIdx.x & 31;
    const int row = blockIdx.x * 8 + wid;
    const bool nat = __ldg(x + (size_t)row * XLD + FEAT) > 0.5f;
    const float* __restrict__ Wc = nat ? Wcn : Wco;
    const float* __restrict__ bc = nat ? bcn : bco;
    const float* zr = g_Z + (size_t)row * PROJ;

    float4 zv[4];
    float ss = 0.f, l0 = 0.f, l1 = 0.f, l2 = 0.f;
    #pragma unroll
    for (int i = 0; i < 4; i++) {
        const int k = i * 128 + lane * 4;
        float4 z = __ldg((const float4*)(zr + k));
        zv[i] = z;
        ss += z.x*z.x + z.y*z.y + z.z*z.z + z.w*z.w;
        float r0 = fmaxf(z.x, 0.f), r1 = fmaxf(z.y, 0.f);
        float r2 = fmaxf(z.z, 0.f), r3 = fmaxf(z.w, 0.f);
        const float4 w0 = __ldg((const float4*)(Wc + k * 3));
        const float4 w1 = __ldg((const float4*)(Wc + k * 3 + 4));
        const float4 w2 = __ldg((const float4*)(Wc + k * 3 + 8));
        l0 += r0*w0.x + r1*w0.w + r2*w1.z + r3*w2.y;
        l1 += r0*w0.y + r1*w1.x + r2*w1.w + r3*w2.z;
        l2 += r0*w0.z + r1*w1.y + r2*w2.x + r3*w2.w;
    }
    #pragma unroll
    for (int o = 16; o > 0; o >>= 1) {
        ss += __shfl_xor_sync(0xFFFFFFFFu, ss, o);
        l0 += __shfl_xor_sync(0xFFFFFFFFu, l0, o);
        l1 += __shfl_xor_sync(0xFFFFFFFFu, l1, o);
        l2 += __shfl_xor_sync(0xFFFFFFFFu, l2, o);
    }
    if (lane == 0) {
        float* lg = out + (size_t)B_ * PROJ + (size_t)row * NOUT;
        lg[0] = l0 + bc[0]; lg[1] = l1 + bc[1]; lg[2] = l2 + bc[2];
    }
    const float inv = 1.f / fmaxf(sqrtf(ss), 1e-12f);
    float* op = out + (size_t)row * PROJ;
    #pragma unroll
    for (int i = 0; i < 4; i++) {
        float4 z = zv[i];
        z.x *= inv; z.y *= inv; z.z *= inv; z.w *= inv;
        *(float4*)(op + i * 128 + lane * 4) = z;
    }
}

// ---------- launcher ----------
extern "C" void kernel_launch(void* const* d_in, const int* in_sizes, int n_in,
                              void* d_out, int out_size) {
    const float* x   = (const float*)d_in[0];
    const float* W1n = (const float*)d_in[1];
    const float* b1n = (const float*)d_in[2];
    const float* W2n = (const float*)d_in[3];
    const float* b2n = (const float*)d_in[4];
    const float* Wcn = (const float*)d_in[5];
    const float* bcn = (const float*)d_in[6];
    const float* W1o = (const float*)d_in[7];
    const float* b1o = (const float*)d_in[8];
    const float* W2o = (const float*)d_in[9];
    const float* b2o = (const float*)d_in[10];
    const float* Wco = (const float*)d_in[11];
    const float* bco = (const float*)d_in[12];
    float* out = (float*)d_out;

    cudaFuncSetAttribute(gemm1, cudaFuncAttributeMaxDynamicSharedMemorySize, 3*32768);
    cudaFuncSetAttribute(gemm2, cudaFuncAttributeMaxDynamicSharedMemorySize, 3*49152);

    k_acw<<<B_ + 2304, 256>>>(x, W1n, W1o, W2n, W2o);
    gemm1<<<dim3(16, TILES_M), 256, 3*32768>>>(b1n, b1o);
    gemm2<<<dim3(4, TILES_M2), 512, 3*49152>>>(b2n, b2o);
    k_final<<<B_ / 8, 256>>>(x, Wcn, bcn, Wco, bco, out);
}

// round 17
// speedup vs baseline: 1.0189x; 1.0189x over previous
#include <cuda_runtime.h>
#include <cuda_fp16.h>
#include <cstdint>

#define B_   32768
#define FEAT 4096
#define XLD  4097
#define HID  2048
#define PROJ 512
#define NOUT 3
#define APAD (B_ + 256)
#define TILES_M 258

// ---------- device scratch ----------
__device__ int g_cnt2[2];
__device__ int g_pos2row[APAD];
__device__ float g_Z[(size_t)B_ * PROJ];
__device__ __half g_A[(size_t)APAD * FEAT];      // fp16 x features, permuted rows (pad rows stay 0)
__device__ __half g_H[(size_t)APAD * HID];       // fp16 hidden
__device__ __half g_W1[(size_t)2 * 16 * 64 * 8192];   // fp16, [N][K] tile-linear SW128 (16KB tiles)
__device__ __half g_W2[(size_t)2 * 4 * 32 * 8192];

// ---------- helpers ----------
__device__ __forceinline__ uint32_t smem_u32(const void* p) {
    uint32_t a;
    asm("{ .reg .u64 t; cvta.to.shared.u64 t, %1; cvt.u32.u64 %0, t; }" : "=r"(a) : "l"(p));
    return a;
}
__device__ __forceinline__ void cpa16(uint32_t d, const void* s) {
    asm volatile("cp.async.cg.shared.global [%0], [%1], 16;" :: "r"(d), "l"(s));
}
#define CPCOMMIT() asm volatile("cp.async.commit_group;" ::: "memory")
#define CPWAIT0()  asm volatile("cp.async.wait_group 0;" ::: "memory")
#define CPWAIT1()  asm volatile("cp.async.wait_group 1;" ::: "memory")
__device__ __forceinline__ void ldsm4(uint32_t* r, uint32_t a) {
    asm volatile("ldmatrix.sync.aligned.m8n8.x4.shared.b16 {%0,%1,%2,%3}, [%4];"
                 : "=r"(r[0]), "=r"(r[1]), "=r"(r[2]), "=r"(r[3]) : "r"(a));
}
__device__ __forceinline__ void mma_h(float* c, const uint32_t* a, const uint32_t* b) {
    asm volatile("mma.sync.aligned.m16n8k16.row.col.f32.f16.f16.f32 "
                 "{%0,%1,%2,%3}, {%4,%5,%6,%7}, {%8,%9}, {%0,%1,%2,%3};"
                 : "+f"(c[0]), "+f"(c[1]), "+f"(c[2]), "+f"(c[3])
                 : "r"(a[0]), "r"(a[1]), "r"(a[2]), "r"(a[3]), "r"(b[0]), "r"(b[1]));
}

// ---------- fused partition + A convert + W prepack (block-range dispatch) ----------
__global__ __launch_bounds__(256) void k_acw(
    const float* __restrict__ x,
    const float* __restrict__ W1n, const float* __restrict__ W1o,
    const float* __restrict__ W2n, const float* __restrict__ W2o)
{
    const int t = threadIdx.x;
    if (blockIdx.x < B_) {
        // ---- partition + convert one original row ----
        const int r = blockIdx.x;
        __shared__ int sPos;
        const int m = r & 3;                        // row-uniform misalignment (XLD ≡ 1 mod 4)
        const float* base = x + (size_t)r * XLD + t * 16 - m;
        float f[20];
        float v[16];
        if (m == 0) {
            #pragma unroll
            for (int q = 0; q < 4; q++) *(float4*)(f + 4*q) = __ldg((const float4*)(base + 4*q));
            #pragma unroll
            for (int j = 0; j < 16; j++) v[j] = f[j];
        } else {
            #pragma unroll
            for (int q = 0; q < 5; q++) *(float4*)(f + 4*q) = __ldg((const float4*)(base + 4*q));
            if (m == 1) {
                #pragma unroll
                for (int j = 0; j < 16; j++) v[j] = f[j + 1];
            } else if (m == 2) {
                #pragma unroll
                for (int j = 0; j < 16; j++) v[j] = f[j + 2];
            } else {
                #pragma unroll
                for (int j = 0; j < 16; j++) v[j] = f[j + 3];
            }
        }
        if (t == 0) {
            bool nat = x[(size_t)r * XLD + FEAT] > 0.5f;
            int idx = atomicAdd(&g_cnt2[nat ? 0 : 1], 1);
            int pos = nat ? idx : (APAD - 1 - idx);
            g_pos2row[pos] = r;
            sPos = pos;
        }
        uint4 h0, h1;
        uint32_t* p0 = (uint32_t*)&h0;
        uint32_t* p1 = (uint32_t*)&h1;
        #pragma unroll
        for (int e = 0; e < 4; e++) {
            __half2 a = __floats2half2_rn(v[2*e],   v[2*e+1]);
            __half2 b = __floats2half2_rn(v[8+2*e], v[8+2*e+1]);
            p0[e] = *reinterpret_cast<uint32_t*>(&a);
            p1[e] = *reinterpret_cast<uint32_t*>(&b);
        }
        __syncthreads();
        size_t db = ((size_t)sPos * FEAT + t * 16) * 2;
        *(uint4*)((char*)g_A + db)      = h0;
        *(uint4*)((char*)g_A + db + 16) = h1;
        return;
    }

    // ---- W prepack ----
    int b = blockIdx.x - B_;
    float rv[8][4];
    if (b < 2048) {
        int tid = b * 256 + t;
        int n = (tid & 511) * 4;
        int rest = tid >> 9;
        int ko = rest & 511, g = rest >> 9;
        const float* src = (g ? W1o : W1n) + (size_t)(ko * 8) * HID + n;
        #pragma unroll
        for (int j = 0; j < 8; j++)
            *(float4*)rv[j] = __ldg((const float4*)(src + (size_t)j * HID));
        int kt = ko >> 3, cb = ko & 7;
        int nt = n >> 7;
        size_t tb = ((size_t)(((g << 4) + nt) * 64 + kt)) << 14;
        #pragma unroll
        for (int c = 0; c < 4; c++) {
            uint4 hv;
            uint32_t* hp = (uint32_t*)&hv;
            #pragma unroll
            for (int e = 0; e < 4; e++) {
                __half2 p = __floats2half2_rn(rv[2*e][c], rv[2*e+1][c]);
                hp[e] = *reinterpret_cast<uint32_t*>(&p);
            }
            int rIn = (n + c) & 127;
            uint32_t sw = (uint32_t)(rIn * 128 + (cb << 4)) ^ ((uint32_t)(rIn & 7) << 4);
            *(uint4*)((char*)g_W1 + tb + sw) = hv;
        }
    } else {
        int tid = (b - 2048) * 256 + t;
        int n = (tid & 127) * 4;
        int rest = tid >> 7;
        int ko = rest & 255, g = rest >> 8;
        const float* src = (g ? W2o : W2n) + (size_t)(ko * 8) * PROJ + n;
        #pragma unroll
        for (int j = 0; j < 8; j++)
            *(float4*)rv[j] = __ldg((const float4*)(src + (size_t)j * PROJ));
        int kt = ko >> 3, cb = ko & 7;
        int nt = n >> 7;
        size_t tb = ((size_t)(((g << 2) + nt) * 32 + kt)) << 14;
        #pragma unroll
        for (int c = 0; c < 4; c++) {
            uint4 hv;
            uint32_t* hp = (uint32_t*)&hv;
            #pragma unroll
            for (int e = 0; e < 4; e++) {
                __half2 p = __floats2half2_rn(rv[2*e][c], rv[2*e+1][c]);
                hp[e] = *reinterpret_cast<uint32_t*>(&p);
            }
            int rIn = (n + c) & 127;
            uint32_t sw = (uint32_t)(rIn * 128 + (cb << 4)) ^ ((uint32_t)(rIn & 7) << 4);
            *(uint4*)((char*)g_W2 + tb + sw) = hv;
        }
    }
}

// ---------- GEMM: M128 x N128 CTA, warp tile 64x32, K-step 64, 3-stage, 2 CTAs/SM ----------
template <int IS_G1>
__global__ __launch_bounds__(256, 2) void gemm_mma(
    const float* __restrict__ bn_, const float* __restrict__ bo_)
{
    extern __shared__ char smc[];
    __shared__ float biasS[128];
    __shared__ int rowS[128];

    constexpr int STG  = 32768;
    constexpr int NTB  = IS_G1 ? 16 : 4;
    constexpr int KTB  = IS_G1 ? 64 : 32;
    constexpr int NIT  = IS_G1 ? (FEAT/64) : (HID/64);
    const int n_nat = g_cnt2[0], n_oth = g_cnt2[1];
    const int nat_tiles = (n_nat + 127) >> 7;
    const int oth_start = (APAD - n_oth) >> 7;
    const int bm = blockIdx.y, bnb = blockIdx.x;
    int grp;
    if (bm < nat_tiles)       grp = 0;
    else if (bm >= oth_start) grp = 1;
    else return;
    const int prow0 = bm << 7;
    const int lo = grp ? (APAD - n_oth) : 0;
    const int hi = grp ? APAD : n_nat;

    const int t = threadIdx.x;
    const uint32_t sb = smem_u32(smc);
    const char* Asrc = IS_G1 ? (const char*)g_A : (const char*)g_H;
    const size_t rowE = IS_G1 ? FEAT : HID;
    const char* Wsrc = IS_G1 ? (const char*)g_W1 : (const char*)g_W2;

    auto issue = [&](int s, int it) {
        uint32_t base = sb + s * STG;
        #pragma unroll
        for (int i = 0; i < 4; i++) {
            int cid = i * 256 + t;
            int r = cid >> 3, c = cid & 7;
            uint32_t off = (uint32_t)((r * 128 + c * 16) ^ ((r & 7) << 4));
            size_t so = ((size_t)(prow0 + r) * rowE + it * 64 + c * 8) * 2;
            cpa16(base + off, Asrc + so);
        }
        size_t tb0 = ((size_t)((grp * NTB + bnb) * KTB + it)) << 14;
        #pragma unroll
        for (int i = 0; i < 4; i++) {
            int j = i * 256 + t;
            cpa16(base + 16384 + j * 16, Wsrc + tb0 + (size_t)j * 16);
        }
    };

    issue(0, 0); CPCOMMIT();
    issue(1, 1); CPCOMMIT();

    if (t < 128) {
        biasS[t] = (grp ? bo_ : bn_)[(bnb << 7) + t];
        int pos = prow0 + t;
        rowS[t] = (pos >= lo && pos < hi) ? g_pos2row[pos] : -1;
    }

    const int w = t >> 5, lane = t & 31;
    const int wm = w >> 2, wn = w & 3;
    const int lr = lane & 7, gq = lane >> 3;
    int preA[4], rxA[4], preB[2], rxB[2];
    #pragma unroll
    for (int mf = 0; mf < 4; mf++) {
        int row = wm * 64 + mf * 16 + (gq & 1) * 8 + lr;
        preA[mf] = row * 128 + (gq >> 1) * 16;
        rxA[mf]  = (row & 7) << 4;
    }
    #pragma unroll
    for (int p = 0; p < 2; p++) {
        int n = wn * 32 + p * 16 + (gq >> 1) * 8 + lr;
        preB[p] = (n & 127) * 128 + (gq & 1) * 16;
        rxB[p]  = (n & 7) << 4;
    }

    float acc[4][4][4];
    #pragma unroll
    for (int i = 0; i < 4; i++)
        #pragma unroll
        for (int j = 0; j < 4; j++)
            #pragma unroll
            for (int e = 0; e < 4; e++) acc[i][j][e] = 0.f;

    int buf = 0, nbuf = 2;
    for (int it = 0; it < NIT; it++) {
        if (it + 1 < NIT) { CPWAIT1(); }
        else              { CPWAIT0(); }
        __syncthreads();
        uint32_t sA = sb + buf * STG, sW = sA + 16384;
        #pragma unroll
        for (int k16 = 0; k16 < 4; k16++) {
            int kb = k16 * 32;
            uint32_t a[4][4], bb[4][2];
            #pragma unroll
            for (int mf = 0; mf < 4; mf++) ldsm4(a[mf], sA + (uint32_t)((preA[mf] + kb) ^ rxA[mf]));
            #pragma unroll
            for (int p = 0; p < 2; p++) {
                uint32_t r[4];
                ldsm4(r, sW + (uint32_t)((preB[p] + kb) ^ rxB[p]));
                bb[2*p][0]=r[0]; bb[2*p][1]=r[1]; bb[2*p+1][0]=r[2]; bb[2*p+1][1]=r[3];
            }
            #pragma unroll
            for (int mf = 0; mf < 4; mf++)
                #pragma unroll
                for (int nf = 0; nf < 4; nf++) mma_h(acc[mf][nf], a[mf], bb[nf]);
            if (k16 == 0 && it + 2 < NIT) { issue(nbuf, it + 2); CPCOMMIT(); }
        }
        buf = (buf == 2) ? 0 : buf + 1;
        nbuf = (nbuf == 2) ? 0 : nbuf + 1;
    }

    #pragma unroll
    for (int mf = 0; mf < 4; mf++) {
        #pragma unroll
        for (int half = 0; half < 2; half++) {
            int row = wm * 64 + mf * 16 + (lane >> 2) + half * 8;
            if (IS_G1) {
                size_t base = (size_t)(prow0 + row) * HID + (bnb << 7);
                #pragma unroll
                for (int nf = 0; nf < 4; nf++) {
                    int n = wn * 32 + nf * 8 + (lane & 3) * 2;
                    float v0 = fmaxf(acc[mf][nf][half*2+0] + biasS[n],     0.f);
                    float v1 = fmaxf(acc[mf][nf][half*2+1] + biasS[n + 1], 0.f);
                    __half2 p = __floats2half2_rn(v0, v1);
                    *(uint32_t*)((char*)g_H + (base + n) * 2) = *reinterpret_cast<uint32_t*>(&p);
                }
            } else {
                int orig = rowS[row];
                if (orig >= 0) {
                    float* zp = g_Z + (size_t)orig * PROJ + (bnb << 7);
                    #pragma unroll
                    for (int nf = 0; nf < 4; nf++) {
                        int n = wn * 32 + nf * 8 + (lane & 3) * 2;
                        float2 v;
                        v.x = acc[mf][nf][half*2+0] + biasS[n];
                        v.y = acc[mf][nf][half*2+1] + biasS[n + 1];
                        *(float2*)(zp + n) = v;
                    }
                }
            }
        }
    }
}

// ---------- finalize: warp-per-row norm + logits; resets counters for next replay ----------
__global__ __launch_bounds__(256) void k_final(
    const float* __restrict__ x,
    const float* __restrict__ Wcn, const float* __restrict__ bcn,
    const float* __restrict__ Wco, const float* __restrict__ bco,
    float* __restrict__ out)
{
    if (blockIdx.x == 0 && threadIdx.x == 0) {
        g_cnt2[0] = 0; g_cnt2[1] = 0;
    }
    const int wid = threadIdx.x >> 5, lane = threadIdx.x & 31;
    const int row = blockIdx.x * 8 + wid;
    const bool nat = __ldg(x + (size_t)row * XLD + FEAT) > 0.5f;
    const float* __restrict__ Wc = nat ? Wcn : Wco;
    const float* __restrict__ bc = nat ? bcn : bco;
    const float* zr = g_Z + (size_t)row * PROJ;

    float4 zv[4];
    float ss = 0.f, l0 = 0.f, l1 = 0.f, l2 = 0.f;
    #pragma unroll
    for (int i = 0; i < 4; i++) {
        const int k = i * 128 + lane * 4;
        float4 z = __ldg((const float4*)(zr + k));
        zv[i] = z;
        ss += z.x*z.x + z.y*z.y + z.z*z.z + z.w*z.w;
        float r0 = fmaxf(z.x, 0.f), r1 = fmaxf(z.y, 0.f);
        float r2 = fmaxf(z.z, 0.f), r3 = fmaxf(z.w, 0.f);
        const float4 w0 = __ldg((const float4*)(Wc + k * 3));
        const float4 w1 = __ldg((const float4*)(Wc + k * 3 + 4));
        const float4 w2 = __ldg((const float4*)(Wc + k * 3 + 8));
        l0 += r0*w0.x + r1*w0.w + r2*w1.z + r3*w2.y;
        l1 += r0*w0.y + r1*w1.x + r2*w1.w + r3*w2.z;
        l2 += r0*w0.z + r1*w1.y + r2*w2.x + r3*w2.w;
    }
    #pragma unroll
    for (int o = 16; o > 0; o >>= 1) {
        ss += __shfl_xor_sync(0xFFFFFFFFu, ss, o);
        l0 += __shfl_xor_sync(0xFFFFFFFFu, l0, o);
        l1 += __shfl_xor_sync(0xFFFFFFFFu, l1, o);
        l2 += __shfl_xor_sync(0xFFFFFFFFu, l2, o);
    }
    if (lane == 0) {
        float* lg = out + (size_t)B_ * PROJ + (size_t)row * NOUT;
        lg[0] = l0 + bc[0]; lg[1] = l1 + bc[1]; lg[2] = l2 + bc[2];
    }
    const float inv = 1.f / fmaxf(sqrtf(ss), 1e-12f);
    float* op = out + (size_t)row * PROJ;
    #pragma unroll
    for (int i = 0; i < 4; i++) {
        float4 z = zv[i];
        z.x *= inv; z.y *= inv; z.z *= inv; z.w *= inv;
        *(float4*)(op + i * 128 + lane * 4) = z;
    }
}

// ---------- launcher ----------
extern "C" void kernel_launch(void* const* d_in, const int* in_sizes, int n_in,
                              void* d_out, int out_size) {
    const float* x   = (const float*)d_in[0];
    const float* W1n = (const float*)d_in[1];
    const float* b1n = (const float*)d_in[2];
    const float* W2n = (const float*)d_in[3];
    const float* b2n = (const float*)d_in[4];
    const float* Wcn = (const float*)d_in[5];
    const float* bcn = (const float*)d_in[6];
    const float* W1o = (const float*)d_in[7];
    const float* b1o = (const float*)d_in[8];
    const float* W2o = (const float*)d_in[9];
    const float* b2o = (const float*)d_in[10];
    const float* Wco = (const float*)d_in[11];
    const float* bco = (const float*)d_in[12];
    float* out = (float*)d_out;

    cudaFuncSetAttribute(gemm_mma<1>, cudaFuncAttributeMaxDynamicSharedMemorySize, 3*32768);
    cudaFuncSetAttribute(gemm_mma<0>, cudaFuncAttributeMaxDynamicSharedMemorySize, 3*32768);

    k_acw<<<B_ + 2304, 256>>>(x, W1n, W1o, W2n, W2o);
    gemm_mma<1><<<dim3(16, TILES_M), 256, 3*32768>>>(b1n, b1o);
    gemm_mma<0><<<dim3(4, TILES_M), 256, 3*32768>>>(b2n, b2o);
    k_final<<<B_ / 8, 256>>>(x, Wcn, bcn, Wco, bco, out);
}